// round 8
// baseline (speedup 1.0000x reference)
#include <cuda_runtime.h>
#include <cstdint>
#include <math.h>

#define HEAD 64
#define NEMB 1024
#define BATCH 8
#define SEQ   2048
#define MTOT  (BATCH*SEQ)   // 16384
#define NTB   (SEQ/64)      // 32 t-blocks per batch

// scratch: projected k,q,v fp32 (12.6 MB) + transposed tf32-rounded weights
__device__ float g_kqv[3][MTOT][HEAD];
__device__ float g_Wt[3][HEAD][NEMB];   // Wt[p][n][k] = rna_tf32(W[p][k][n])

__device__ __forceinline__ float to_tf32(float x) {
    float y; asm("cvt.rna.tf32.f32 %0, %1;" : "=f"(y) : "f"(x)); return y;
}
__device__ __forceinline__ uint32_t to_tf32_bits(float x) {
    float y; asm("cvt.rna.tf32.f32 %0, %1;" : "=f"(y) : "f"(x));
    return __float_as_uint(y);
}

// D += A*B : m16n8k8 tf32 (A row-major frag, B col-major frag), fp32 accum
__device__ __forceinline__ void mma8(float c[4], const uint32_t a[4], uint32_t b0, uint32_t b1) {
    asm volatile(
        "mma.sync.aligned.m16n8k8.row.col.f32.tf32.tf32.f32 "
        "{%0,%1,%2,%3}, {%4,%5,%6,%7}, {%8,%9}, {%0,%1,%2,%3};"
        : "+f"(c[0]), "+f"(c[1]), "+f"(c[2]), "+f"(c[3])
        : "r"(a[0]), "r"(a[1]), "r"(a[2]), "r"(a[3]), "r"(b0), "r"(b1));
}

#define BARH(id) asm volatile("bar.sync %0, 256;" :: "r"(id) : "memory")

// ---------------------------------------------------------------------------
// W transpose + tf32 pre-round:  g_Wt[p][n][k] = rna(W[p][k][n])
// grid (64, 3): each block transposes a 16(k) x 64(n) tile (4 elems/thread).
// ---------------------------------------------------------------------------
__global__ __launch_bounds__(256) void wt_kernel(
    const float* __restrict__ Wk, const float* __restrict__ Wq, const float* __restrict__ Wv)
{
    __shared__ float t[64][17];
    const float* __restrict__ W = (blockIdx.y == 0) ? Wk : ((blockIdx.y == 1) ? Wq : Wv);
    const int k0 = blockIdx.x * 16;
    const int tid = threadIdx.x;
    #pragma unroll
    for (int i = 0; i < 4; ++i) {
        int idx = i * 256 + tid;          // 0..1023
        int kk = idx >> 6, n = idx & 63;  // consecutive tid -> consecutive n (coalesced read)
        t[n][kk] = to_tf32(W[(size_t)(k0 + kk) * HEAD + n]);
    }
    __syncthreads();
    #pragma unroll
    for (int i = 0; i < 4; ++i) {
        int idx = i * 256 + tid;
        int n = idx >> 4, kk = idx & 15;  // consecutive tid -> consecutive k (coalesced write)
        g_Wt[blockIdx.y][n][k0 + kk] = t[n][kk];
    }
}

// ---------------------------------------------------------------------------
// Projection via mma.sync tf32. CTA tile: 128(m) x 192(n=3x64), K chunk 32.
// 512 threads, 16 warps in 8(m) x 2(n) grid: warp tile 16 rows x 96 cols.
// smem stride 36 (conflict-free fragment loads). Software-pipelined LDGs.
// ---------------------------------------------------------------------------
__global__ __launch_bounds__(512, 1) void proj_mma_kernel(
    const float* __restrict__ x,
    const float* __restrict__ bk, const float* __restrict__ bq, const float* __restrict__ bv)
{
    __shared__ float xs[128][36];   // [m][k] tf32-rounded
    __shared__ float ws[192][36];   // [n_global][k] tf32-rounded

    const int tid  = threadIdx.x;
    const int wid  = tid >> 5, lane = tid & 31;
    const int wm   = wid >> 1, wn = wid & 1;
    const int g    = lane >> 2, t = lane & 3;
    const int m0   = blockIdx.x * 128;

    // loader indices (fixed per thread)
    int xrow[2], xcol[2], wrow[3], wcol[3];
    #pragma unroll
    for (int i = 0; i < 2; ++i) { int idx = i * 512 + tid; xrow[i] = idx >> 3; xcol[i] = (idx & 7) * 4; }
    #pragma unroll
    for (int i = 0; i < 3; ++i) { int idx = i * 512 + tid; wrow[i] = idx >> 3; wcol[i] = (idx & 7) * 4; }

    float c[12][4];
    #pragma unroll
    for (int nt = 0; nt < 12; ++nt)
        #pragma unroll
        for (int r = 0; r < 4; ++r) c[nt][r] = 0.f;

    float4 xr[2], wr[3];

    // prologue: load chunk 0
    #pragma unroll
    for (int i = 0; i < 2; ++i)
        xr[i] = *(const float4*)&x[(size_t)(m0 + xrow[i]) * NEMB + xcol[i]];
    #pragma unroll
    for (int i = 0; i < 3; ++i)
        wr[i] = *(const float4*)&g_Wt[wrow[i] >> 6][wrow[i] & 63][wcol[i]];
    #pragma unroll
    for (int i = 0; i < 2; ++i) {
        float* d = &xs[xrow[i]][xcol[i]];
        d[0] = to_tf32(xr[i].x); d[1] = to_tf32(xr[i].y); d[2] = to_tf32(xr[i].z); d[3] = to_tf32(xr[i].w);
    }
    #pragma unroll
    for (int i = 0; i < 3; ++i)
        *(float4*)&ws[wrow[i]][wcol[i]] = wr[i];
    __syncthreads();

    for (int ch = 0; ch < 32; ++ch) {
        // prefetch next chunk into registers (overlaps with MMA below)
        if (ch < 31) {
            const int k1 = (ch + 1) * 32;
            #pragma unroll
            for (int i = 0; i < 2; ++i)
                xr[i] = *(const float4*)&x[(size_t)(m0 + xrow[i]) * NEMB + k1 + xcol[i]];
            #pragma unroll
            for (int i = 0; i < 3; ++i)
                wr[i] = *(const float4*)&g_Wt[wrow[i] >> 6][wrow[i] & 63][k1 + wcol[i]];
        }

        // A fragments: 1 m-tile x 4 k-tiles
        uint32_t A[4][4];
        {
            const int row = wm * 16 + g;
            #pragma unroll
            for (int kt = 0; kt < 4; ++kt) {
                const int col = kt * 8 + t;
                A[kt][0] = __float_as_uint(xs[row    ][col    ]);
                A[kt][1] = __float_as_uint(xs[row + 8][col    ]);
                A[kt][2] = __float_as_uint(xs[row    ][col + 4]);
                A[kt][3] = __float_as_uint(xs[row + 8][col + 4]);
            }
        }
        #pragma unroll
        for (int kt = 0; kt < 4; ++kt) {
            #pragma unroll
            for (int nt = 0; nt < 12; ++nt) {
                const int ng = wn * 96 + nt * 8 + g;
                const int col = kt * 8 + t;
                uint32_t b0 = __float_as_uint(ws[ng][col]);
                uint32_t b1 = __float_as_uint(ws[ng][col + 4]);
                mma8(c[nt], A[kt], b0, b1);
            }
        }
        __syncthreads();      // all smem reads of this chunk done

        if (ch < 31) {
            #pragma unroll
            for (int i = 0; i < 2; ++i) {
                float* d = &xs[xrow[i]][xcol[i]];
                d[0] = to_tf32(xr[i].x); d[1] = to_tf32(xr[i].y);
                d[2] = to_tf32(xr[i].z); d[3] = to_tf32(xr[i].w);
            }
            #pragma unroll
            for (int i = 0; i < 3; ++i)
                *(float4*)&ws[wrow[i]][wcol[i]] = wr[i];
            __syncthreads();  // stores visible before next chunk's MMA
        }
    }

    // epilogue: bias + store
    const float* biases[3] = {bk, bq, bv};
    #pragma unroll
    for (int nt = 0; nt < 12; ++nt) {
        const int ng0 = wn * 96 + nt * 8;
        const int p = ng0 >> 6;
        const int n = (ng0 & 63) + 2 * t;
        const float* __restrict__ bias = biases[p];
        const float b0 = bias[n], b1 = bias[n + 1];
        const int row = m0 + wm * 16 + g;
        float2 lo = {c[nt][0] + b0, c[nt][1] + b1};
        float2 hi = {c[nt][2] + b0, c[nt][3] + b1};
        *(float2*)&g_kqv[p][row    ][n] = lo;
        *(float2*)&g_kqv[p][row + 8][n] = hi;
    }
}

// ---------------------------------------------------------------------------
// Attention via mma.sync tf32. 512 threads: warps 0-7 handle t-block i,
// warps 8-15 handle t-block 31-i CONCURRENTLY (per-half named barriers).
// Every CTA does exactly 33 tile-iterations of wallclock work. Grid (16,8).
// ---------------------------------------------------------------------------
#define AST 68
#define HALF_FLOATS (4 * 64 * AST)
#define ATTN_SMEM (2 * HALF_FLOATS * 4)   // 139264 B

__device__ __forceinline__ float softplus_f(float x) {
    return fmaxf(x, 0.f) + __logf(1.f + __expf(-fabsf(x)));
}

__global__ __launch_bounds__(512, 1) void attn_kernel(float* __restrict__ out)
{
    extern __shared__ float sm[];

    const int b    = blockIdx.y;
    const int tid  = threadIdx.x;
    const int half = tid >> 8;            // 0 or 1
    const int tidh = tid & 255;
    const int widh = tidh >> 5, lane = tid & 31;
    const int wm   = widh >> 1, wn = widh & 1;
    const int g    = lane >> 2, t = lane & 3;
    const int lr   = tidh & 63;           // loader row (V)
    const int lh   = (tidh >> 6) * 4;     // loader col base (V)
    const int barid = 1 + half;

    float* ks = sm + half * HALF_FLOATS;            // [64][AST]  K tile [t][h]
    float* qs = ks + 64 * AST;                      // [64][AST]  Q tile [s][h]
    float* vT = ks + 2 * 64 * AST;                  // [64][AST]  V transposed [h][s]
    float* Ps = ks + 3 * 64 * AST;                  // [64][AST]  P tile [t][s]

    const int tb = half ? (NTB - 1 - (int)blockIdx.x) : (int)blockIdx.x;

    // fixed loader indices for K/Q ([row][h] layout)
    int qrow[4], qcol[4];
    #pragma unroll
    for (int i = 0; i < 4; ++i) { int idx = i * 256 + tidh; qrow[i] = idx >> 4; qcol[i] = (idx & 15) * 4; }

    const float* __restrict__ Kg = &g_kqv[0][(size_t)b * SEQ][0];
    const float* __restrict__ Qg = &g_kqv[1][(size_t)b * SEQ][0];
    const float* __restrict__ Vg = &g_kqv[2][(size_t)b * SEQ][0];

    // K tile [t][h], tf32-rounded
    #pragma unroll
    for (int i = 0; i < 4; ++i) {
        float4 v = *(const float4*)&Kg[(size_t)(tb * 64 + qrow[i]) * HEAD + qcol[i]];
        float* d = &ks[qrow[i] * AST + qcol[i]];
        d[0] = to_tf32(v.x); d[1] = to_tf32(v.y); d[2] = to_tf32(v.z); d[3] = to_tf32(v.w);
    }

    const int trow = wm * 16 + g;

    float o[4][4];
    #pragma unroll
    for (int nt = 0; nt < 4; ++nt)
        #pragma unroll
        for (int r = 0; r < 4; ++r) o[nt][r] = 0.f;

    // prologue: load sb=0 tiles into smem (overlaps K-tile barrier)
    float4 qr[4], vr[4];
    #pragma unroll
    for (int i = 0; i < 4; ++i)
        qr[i] = *(const float4*)&Qg[(size_t)qrow[i] * HEAD + qcol[i]];
    #pragma unroll
    for (int r = 0; r < 4; ++r)
        vr[r] = *(const float4*)&Vg[(size_t)lr * HEAD + (lh + r * 16)];
    #pragma unroll
    for (int i = 0; i < 4; ++i) {
        float* d = &qs[qrow[i] * AST + qcol[i]];
        d[0] = to_tf32(qr[i].x); d[1] = to_tf32(qr[i].y); d[2] = to_tf32(qr[i].z); d[3] = to_tf32(qr[i].w);
    }
    #pragma unroll
    for (int r = 0; r < 4; ++r) {
        int hh = lh + r * 16;
        vT[(hh + 0) * AST + lr] = to_tf32(vr[r].x);
        vT[(hh + 1) * AST + lr] = to_tf32(vr[r].y);
        vT[(hh + 2) * AST + lr] = to_tf32(vr[r].z);
        vT[(hh + 3) * AST + lr] = to_tf32(vr[r].w);
    }
    BARH(barid);

    for (int sb = 0; sb <= tb; ++sb) {
        // prefetch next tiles into registers (overlaps S-phase + O-phase)
        if (sb < tb) {
            const size_t s1 = (size_t)(sb + 1) * 64;
            #pragma unroll
            for (int i = 0; i < 4; ++i)
                qr[i] = *(const float4*)&Qg[(s1 + qrow[i]) * HEAD + qcol[i]];
            #pragma unroll
            for (int r = 0; r < 4; ++r)
                vr[r] = *(const float4*)&Vg[(s1 + lr) * HEAD + (lh + r * 16)];
        }

        // S = K . Q^T  (contract over h); K fragments rebuilt per kt (reg relief)
        float s_c[4][4];
        #pragma unroll
        for (int nt = 0; nt < 4; ++nt)
            #pragma unroll
            for (int r = 0; r < 4; ++r) s_c[nt][r] = 0.f;
        #pragma unroll
        for (int kt = 0; kt < 8; ++kt) {
            const int col = kt * 8 + t;
            uint32_t A[4];
            A[0] = __float_as_uint(ks[(trow    ) * AST + col    ]);
            A[1] = __float_as_uint(ks[(trow + 8) * AST + col    ]);
            A[2] = __float_as_uint(ks[(trow    ) * AST + col + 4]);
            A[3] = __float_as_uint(ks[(trow + 8) * AST + col + 4]);
            #pragma unroll
            for (int nt = 0; nt < 4; ++nt) {
                const int srow = wn * 32 + nt * 8 + g;
                uint32_t b0 = __float_as_uint(qs[srow * AST + col    ]);
                uint32_t b1 = __float_as_uint(qs[srow * AST + col + 4]);
                mma8(s_c[nt], A, b0, b1);
            }
        }

        // softplus + causal mask -> Ps [t][s]
        const bool diag = (sb == tb);
        #pragma unroll
        for (int nt = 0; nt < 4; ++nt) {
            const int sc = wn * 32 + nt * 8 + 2 * t;
            float p0 = softplus_f(s_c[nt][0] * 0.03125f);
            float p1 = softplus_f(s_c[nt][1] * 0.03125f);
            float p2 = softplus_f(s_c[nt][2] * 0.03125f);
            float p3 = softplus_f(s_c[nt][3] * 0.03125f);
            if (diag) {
                if (sc     > trow    ) p0 = 0.f;
                if (sc + 1 > trow    ) p1 = 0.f;
                if (sc     > trow + 8) p2 = 0.f;
                if (sc + 1 > trow + 8) p3 = 0.f;
            }
            *(float2*)&Ps[(trow    ) * AST + sc] = make_float2(p0, p1);
            *(float2*)&Ps[(trow + 8) * AST + sc] = make_float2(p2, p3);
        }
        BARH(barid);   // Ps visible to this half's warps

        // O += P . V  (contract over s)
        #pragma unroll
        for (int kt = 0; kt < 8; ++kt) {
            const int col = kt * 8 + t;
            uint32_t pa[4];
            pa[0] = to_tf32_bits(Ps[(trow    ) * AST + col    ]);
            pa[1] = to_tf32_bits(Ps[(trow + 8) * AST + col    ]);
            pa[2] = to_tf32_bits(Ps[(trow    ) * AST + col + 4]);
            pa[3] = to_tf32_bits(Ps[(trow + 8) * AST + col + 4]);
            #pragma unroll
            for (int nt = 0; nt < 4; ++nt) {
                const int hrow = wn * 32 + nt * 8 + g;
                uint32_t b0 = __float_as_uint(vT[hrow * AST + col    ]);
                uint32_t b1 = __float_as_uint(vT[hrow * AST + col + 4]);
                mma8(o[nt], pa, b0, b1);
            }
        }
        BARH(barid);   // all reads of qs/vT done

        if (sb < tb) {
            #pragma unroll
            for (int i = 0; i < 4; ++i) {
                float* d = &qs[qrow[i] * AST + qcol[i]];
                d[0] = to_tf32(qr[i].x); d[1] = to_tf32(qr[i].y);
                d[2] = to_tf32(qr[i].z); d[3] = to_tf32(qr[i].w);
            }
            #pragma unroll
            for (int r = 0; r < 4; ++r) {
                int hh = lh + r * 16;
                vT[(hh + 0) * AST + lr] = to_tf32(vr[r].x);
                vT[(hh + 1) * AST + lr] = to_tf32(vr[r].y);
                vT[(hh + 2) * AST + lr] = to_tf32(vr[r].z);
                vT[(hh + 3) * AST + lr] = to_tf32(vr[r].w);
            }
            BARH(barid);  // stores visible before next S-MMA
        }
    }

    // write O tile
    {
        const size_t row0 = (size_t)b * SEQ + tb * 64 + trow;
        #pragma unroll
        for (int nt = 0; nt < 4; ++nt) {
            const int col = wn * 32 + nt * 8 + 2 * t;
            *(float2*)&out[(row0    ) * HEAD + col] = make_float2(o[nt][0], o[nt][1]);
            *(float2*)&out[(row0 + 8) * HEAD + col] = make_float2(o[nt][2], o[nt][3]);
        }
    }
}

// ---------------------------------------------------------------------------
extern "C" void kernel_launch(void* const* d_in, const int* in_sizes, int n_in,
                              void* d_out, int out_size)
{
    const float* x  = (const float*)d_in[0];
    const float* Wk = (const float*)d_in[1];
    const float* bk = (const float*)d_in[2];
    const float* Wq = (const float*)d_in[3];
    const float* bq = (const float*)d_in[4];
    const float* Wv = (const float*)d_in[5];
    const float* bv = (const float*)d_in[6];
    float* out = (float*)d_out;

    static int init = 0;
    if (!init) {
        cudaFuncSetAttribute(attn_kernel, cudaFuncAttributeMaxDynamicSharedMemorySize, ATTN_SMEM);
        init = 1;
    }

    dim3 wg(NEMB / 16, 3);
    wt_kernel<<<wg, 256>>>(Wk, Wq, Wv);

    proj_mma_kernel<<<MTOT / 128, 512>>>(x, bk, bq, bv);

    dim3 ag(NTB / 2, BATCH);
    attn_kernel<<<ag, 512, ATTN_SMEM>>>(out);
}

// round 9
// speedup vs baseline: 1.3081x; 1.3081x over previous
#include <cuda_runtime.h>
#include <cuda_fp16.h>
#include <cstdint>
#include <math.h>

#define HEAD 64
#define NEMB 1024
#define BATCH 8
#define SEQ   2048
#define MTOT  (BATCH*SEQ)   // 16384
#define NTB   (SEQ/64)      // 32 t-blocks per batch

// scratch: projected k,q,v fp32 (12.6 MB) + transposed tf32-rounded weights
__device__ float g_kqv[3][MTOT][HEAD];
__device__ float g_Wt[3][HEAD][NEMB];   // Wt[p][n][k] = rna_tf32(W[p][k][n])

__device__ __forceinline__ float to_tf32(float x) {
    float y; asm("cvt.rna.tf32.f32 %0, %1;" : "=f"(y) : "f"(x)); return y;
}

// D += A*B : m16n8k8 tf32 (A row-major frag, B col-major frag), fp32 accum
__device__ __forceinline__ void mma8(float c[4], const uint32_t a[4], uint32_t b0, uint32_t b1) {
    asm volatile(
        "mma.sync.aligned.m16n8k8.row.col.f32.tf32.tf32.f32 "
        "{%0,%1,%2,%3}, {%4,%5,%6,%7}, {%8,%9}, {%0,%1,%2,%3};"
        : "+f"(c[0]), "+f"(c[1]), "+f"(c[2]), "+f"(c[3])
        : "r"(a[0]), "r"(a[1]), "r"(a[2]), "r"(a[3]), "r"(b0), "r"(b1));
}

// D += A*B : m16n8k16 fp16 inputs, fp32 accum
__device__ __forceinline__ void mma16(float c[4], const uint32_t a[4], uint32_t b0, uint32_t b1) {
    asm volatile(
        "mma.sync.aligned.m16n8k16.row.col.f32.f16.f16.f32 "
        "{%0,%1,%2,%3}, {%4,%5,%6,%7}, {%8,%9}, {%0,%1,%2,%3};"
        : "+f"(c[0]), "+f"(c[1]), "+f"(c[2]), "+f"(c[3])
        : "r"(a[0]), "r"(a[1]), "r"(a[2]), "r"(a[3]), "r"(b0), "r"(b1));
}

__device__ __forceinline__ uint32_t f2h2(float a, float b) {
    __half2 h = __floats2half2_rn(a, b);
    return *(uint32_t*)&h;
}

// ---------------------------------------------------------------------------
// W transpose + tf32 pre-round:  g_Wt[p][n][k] = rna(W[p][k][n])
// grid (64, 3): each block transposes a 16(k) x 64(n) tile.
// ---------------------------------------------------------------------------
__global__ __launch_bounds__(256) void wt_kernel(
    const float* __restrict__ Wk, const float* __restrict__ Wq, const float* __restrict__ Wv)
{
    __shared__ float t[64][17];
    const float* __restrict__ W = (blockIdx.y == 0) ? Wk : ((blockIdx.y == 1) ? Wq : Wv);
    const int k0 = blockIdx.x * 16;
    const int tid = threadIdx.x;
    #pragma unroll
    for (int i = 0; i < 4; ++i) {
        int idx = i * 256 + tid;
        int kk = idx >> 6, n = idx & 63;
        t[n][kk] = to_tf32(W[(size_t)(k0 + kk) * HEAD + n]);
    }
    __syncthreads();
    #pragma unroll
    for (int i = 0; i < 4; ++i) {
        int idx = i * 256 + tid;
        int n = idx >> 4, kk = idx & 15;
        g_Wt[blockIdx.y][n][k0 + kk] = t[n][kk];
    }
}

// ---------------------------------------------------------------------------
// Projection via mma.sync tf32 (R6 version). CTA: 128(m) x 192(n), K chunk 32.
// 256 threads, 8 warps 4(m) x 2(n). Software-pipelined LDGs.
// ---------------------------------------------------------------------------
__global__ __launch_bounds__(256, 1) void proj_mma_kernel(
    const float* __restrict__ x,
    const float* __restrict__ bk, const float* __restrict__ bq, const float* __restrict__ bv)
{
    __shared__ float xs[128][36];
    __shared__ float ws[192][36];

    const int tid  = threadIdx.x;
    const int wid  = tid >> 5, lane = tid & 31;
    const int wm   = wid >> 1, wn = wid & 1;
    const int g    = lane >> 2, t = lane & 3;
    const int m0   = blockIdx.x * 128;

    int xrow[4], xcol[4], wrow[6], wcol[6];
    #pragma unroll
    for (int i = 0; i < 4; ++i) { int idx = i * 256 + tid; xrow[i] = idx >> 3; xcol[i] = (idx & 7) * 4; }
    #pragma unroll
    for (int i = 0; i < 6; ++i) { int idx = i * 256 + tid; wrow[i] = idx >> 3; wcol[i] = (idx & 7) * 4; }

    float c[2][12][4];
    #pragma unroll
    for (int mt = 0; mt < 2; ++mt)
        #pragma unroll
        for (int nt = 0; nt < 12; ++nt)
            #pragma unroll
            for (int r = 0; r < 4; ++r) c[mt][nt][r] = 0.f;

    float4 xr[4], wr[6];

    #pragma unroll
    for (int i = 0; i < 4; ++i)
        xr[i] = *(const float4*)&x[(size_t)(m0 + xrow[i]) * NEMB + xcol[i]];
    #pragma unroll
    for (int i = 0; i < 6; ++i)
        wr[i] = *(const float4*)&g_Wt[wrow[i] >> 6][wrow[i] & 63][wcol[i]];
    #pragma unroll
    for (int i = 0; i < 4; ++i) {
        float* d = &xs[xrow[i]][xcol[i]];
        d[0] = to_tf32(xr[i].x); d[1] = to_tf32(xr[i].y); d[2] = to_tf32(xr[i].z); d[3] = to_tf32(xr[i].w);
    }
    #pragma unroll
    for (int i = 0; i < 6; ++i)
        *(float4*)&ws[wrow[i]][wcol[i]] = wr[i];
    __syncthreads();

    for (int ch = 0; ch < 32; ++ch) {
        if (ch < 31) {
            const int k1 = (ch + 1) * 32;
            #pragma unroll
            for (int i = 0; i < 4; ++i)
                xr[i] = *(const float4*)&x[(size_t)(m0 + xrow[i]) * NEMB + k1 + xcol[i]];
            #pragma unroll
            for (int i = 0; i < 6; ++i)
                wr[i] = *(const float4*)&g_Wt[wrow[i] >> 6][wrow[i] & 63][k1 + wcol[i]];
        }

        uint32_t A[2][4][4];
        #pragma unroll
        for (int mt = 0; mt < 2; ++mt) {
            const int row = wm * 32 + mt * 16 + g;
            #pragma unroll
            for (int kt = 0; kt < 4; ++kt) {
                const int col = kt * 8 + t;
                A[mt][kt][0] = __float_as_uint(xs[row    ][col    ]);
                A[mt][kt][1] = __float_as_uint(xs[row + 8][col    ]);
                A[mt][kt][2] = __float_as_uint(xs[row    ][col + 4]);
                A[mt][kt][3] = __float_as_uint(xs[row + 8][col + 4]);
            }
        }
        #pragma unroll
        for (int kt = 0; kt < 4; ++kt) {
            #pragma unroll
            for (int nt = 0; nt < 12; ++nt) {
                const int ng = wn * 96 + nt * 8 + g;
                const int col = kt * 8 + t;
                uint32_t b0 = __float_as_uint(ws[ng][col]);
                uint32_t b1 = __float_as_uint(ws[ng][col + 4]);
                mma8(c[0][nt], A[0][kt], b0, b1);
                mma8(c[1][nt], A[1][kt], b0, b1);
            }
        }
        __syncthreads();

        if (ch < 31) {
            #pragma unroll
            for (int i = 0; i < 4; ++i) {
                float* d = &xs[xrow[i]][xcol[i]];
                d[0] = to_tf32(xr[i].x); d[1] = to_tf32(xr[i].y);
                d[2] = to_tf32(xr[i].z); d[3] = to_tf32(xr[i].w);
            }
            #pragma unroll
            for (int i = 0; i < 6; ++i)
                *(float4*)&ws[wrow[i]][wcol[i]] = wr[i];
            __syncthreads();
        }
    }

    const float* biases[3] = {bk, bq, bv};
    #pragma unroll
    for (int nt = 0; nt < 12; ++nt) {
        const int ng0 = wn * 96 + nt * 8;
        const int p = ng0 >> 6;
        const int n = (ng0 & 63) + 2 * t;
        const float* __restrict__ bias = biases[p];
        const float b0 = bias[n], b1 = bias[n + 1];
        #pragma unroll
        for (int mt = 0; mt < 2; ++mt) {
            const int row = m0 + wm * 32 + mt * 16 + g;
            float2 lo = {c[mt][nt][0] + b0, c[mt][nt][1] + b1};
            float2 hi = {c[mt][nt][2] + b0, c[mt][nt][3] + b1};
            *(float2*)&g_kqv[p][row    ][n] = lo;
            *(float2*)&g_kqv[p][row + 8][n] = hi;
        }
    }
}

// ---------------------------------------------------------------------------
// Attention via fp16 mma m16n8k16 (fp32 accum). 256 threads, 64x64 tiles,
// CTA handles t-blocks {i, 31-i} sequentially; grid (16,8), one wave.
// Q/V tiles double-buffered in fp16 -> 2 barriers per s-iteration.
// Row stride 72 halves (36 words = 4 mod 32 -> conflict-free fragments).
// ---------------------------------------------------------------------------
#define ASTH 72
#define TILE_H (64 * ASTH)                  // halves per tile
#define ATTN_SMEM (6 * TILE_H * 2)          // ks + 2*qs + 2*vT + Ps = 55296 B

__device__ __forceinline__ float softplus_f(float x) {
    return fmaxf(x, 0.f) + __logf(1.f + __expf(-fabsf(x)));
}

__global__ __launch_bounds__(256, 1) void attn_kernel(float* __restrict__ out)
{
    extern __shared__ __half smh[];
    __half* ks  = smh;                       // [64][ASTH]  K tile [t][h]
    __half* qsb = smh + TILE_H;              // 2 x [64][ASTH]  Q tiles [s][h]
    __half* vTb = smh + 3 * TILE_H;          // 2 x [64][ASTH]  V transposed [h][s]
    __half* Ps  = smh + 5 * TILE_H;          // [64][ASTH]  P tile [t][s]

    const int b    = blockIdx.y;
    const int tid  = threadIdx.x;
    const int wid  = tid >> 5, lane = tid & 31;
    const int wm   = wid >> 1, wn = wid & 1;
    const int g    = lane >> 2, t = lane & 3;
    const int lr   = tid & 63;               // V loader row (s)
    const int lh   = (tid >> 6) * 4;         // V loader col base (h)
    const int trow = wm * 16 + g;

    int qrow[4], qcol[4];
    #pragma unroll
    for (int i = 0; i < 4; ++i) { int idx = i * 256 + tid; qrow[i] = idx >> 4; qcol[i] = (idx & 15) * 4; }

    const float* __restrict__ Kg = &g_kqv[0][(size_t)b * SEQ][0];
    const float* __restrict__ Qg = &g_kqv[1][(size_t)b * SEQ][0];
    const float* __restrict__ Vg = &g_kqv[2][(size_t)b * SEQ][0];

    for (int hf = 0; hf < 2; ++hf) {
        const int tb = hf ? (NTB - 1 - (int)blockIdx.x) : (int)blockIdx.x;

        // K tile [t][h] fp16
        #pragma unroll
        for (int i = 0; i < 4; ++i) {
            float4 v = *(const float4*)&Kg[(size_t)(tb * 64 + qrow[i]) * HEAD + qcol[i]];
            uint2 u; u.x = f2h2(v.x, v.y); u.y = f2h2(v.z, v.w);
            *(uint2*)&ks[qrow[i] * ASTH + qcol[i]] = u;
        }

        // prologue: sb=0 Q/V into buffer 0
        {
            __half* qs = qsb;
            __half* vT = vTb;
            #pragma unroll
            for (int i = 0; i < 4; ++i) {
                float4 v = *(const float4*)&Qg[(size_t)qrow[i] * HEAD + qcol[i]];
                uint2 u; u.x = f2h2(v.x, v.y); u.y = f2h2(v.z, v.w);
                *(uint2*)&qs[qrow[i] * ASTH + qcol[i]] = u;
            }
            #pragma unroll
            for (int r = 0; r < 4; ++r) {
                int hh = lh + r * 16;
                float4 v = *(const float4*)&Vg[(size_t)lr * HEAD + hh];
                vT[(hh + 0) * ASTH + lr] = __float2half_rn(v.x);
                vT[(hh + 1) * ASTH + lr] = __float2half_rn(v.y);
                vT[(hh + 2) * ASTH + lr] = __float2half_rn(v.z);
                vT[(hh + 3) * ASTH + lr] = __float2half_rn(v.w);
            }
        }
        __syncthreads();

        // K A-fragments, resident across the s-loop (4 kt of k16)
        uint32_t A[4][4];
        #pragma unroll
        for (int kt = 0; kt < 4; ++kt) {
            const int col = kt * 16 + 2 * t;
            A[kt][0] = *(const uint32_t*)&ks[(trow    ) * ASTH + col    ];
            A[kt][1] = *(const uint32_t*)&ks[(trow + 8) * ASTH + col    ];
            A[kt][2] = *(const uint32_t*)&ks[(trow    ) * ASTH + col + 8];
            A[kt][3] = *(const uint32_t*)&ks[(trow + 8) * ASTH + col + 8];
        }

        float o[4][4];
        #pragma unroll
        for (int nt = 0; nt < 4; ++nt)
            #pragma unroll
            for (int r = 0; r < 4; ++r) o[nt][r] = 0.f;

        uint2 qrh[4];
        uint32_t vrh[8];

        for (int sb = 0; sb <= tb; ++sb) {
            const int cur = sb & 1;
            __half* qs = qsb + cur * TILE_H;
            __half* vT = vTb + cur * TILE_H;
            __half* qsn = qsb + (cur ^ 1) * TILE_H;
            __half* vTn = vTb + (cur ^ 1) * TILE_H;

            // prefetch next Q/V, convert to fp16 in registers
            if (sb < tb) {
                const size_t s1 = (size_t)(sb + 1) * 64;
                #pragma unroll
                for (int i = 0; i < 4; ++i) {
                    float4 v = *(const float4*)&Qg[(s1 + qrow[i]) * HEAD + qcol[i]];
                    qrh[i].x = f2h2(v.x, v.y); qrh[i].y = f2h2(v.z, v.w);
                }
                #pragma unroll
                for (int r = 0; r < 4; ++r) {
                    float4 v = *(const float4*)&Vg[(s1 + lr) * HEAD + (lh + r * 16)];
                    vrh[2 * r]     = f2h2(v.x, v.y);
                    vrh[2 * r + 1] = f2h2(v.z, v.w);
                }
            }

            // S = K . Q^T  (contract over h)
            float s_c[4][4];
            #pragma unroll
            for (int nt = 0; nt < 4; ++nt)
                #pragma unroll
                for (int r = 0; r < 4; ++r) s_c[nt][r] = 0.f;
            #pragma unroll
            for (int kt = 0; kt < 4; ++kt) {
                const int col = kt * 16 + 2 * t;
                #pragma unroll
                for (int nt = 0; nt < 4; ++nt) {
                    const int srow = wn * 32 + nt * 8 + g;
                    uint32_t b0 = *(const uint32_t*)&qs[srow * ASTH + col    ];
                    uint32_t b1 = *(const uint32_t*)&qs[srow * ASTH + col + 8];
                    mma16(s_c[nt], A[kt], b0, b1);
                }
            }

            // softplus + causal mask -> Ps [t][s] fp16
            const bool diag = (sb == tb);
            #pragma unroll
            for (int nt = 0; nt < 4; ++nt) {
                const int sc = wn * 32 + nt * 8 + 2 * t;
                float p0 = softplus_f(s_c[nt][0] * 0.03125f);
                float p1 = softplus_f(s_c[nt][1] * 0.03125f);
                float p2 = softplus_f(s_c[nt][2] * 0.03125f);
                float p3 = softplus_f(s_c[nt][3] * 0.03125f);
                if (diag) {
                    if (sc     > trow    ) p0 = 0.f;
                    if (sc + 1 > trow    ) p1 = 0.f;
                    if (sc     > trow + 8) p2 = 0.f;
                    if (sc + 1 > trow + 8) p3 = 0.f;
                }
                *(uint32_t*)&Ps[(trow    ) * ASTH + sc] = f2h2(p0, p1);
                *(uint32_t*)&Ps[(trow + 8) * ASTH + sc] = f2h2(p2, p3);
            }
            __syncthreads();   // Ps visible

            // O += P . V  (contract over s)
            #pragma unroll
            for (int kt = 0; kt < 4; ++kt) {
                const int col = kt * 16 + 2 * t;
                uint32_t pa[4];
                pa[0] = *(const uint32_t*)&Ps[(trow    ) * ASTH + col    ];
                pa[1] = *(const uint32_t*)&Ps[(trow + 8) * ASTH + col    ];
                pa[2] = *(const uint32_t*)&Ps[(trow    ) * ASTH + col + 8];
                pa[3] = *(const uint32_t*)&Ps[(trow + 8) * ASTH + col + 8];
                #pragma unroll
                for (int nt = 0; nt < 4; ++nt) {
                    const int hrow = wn * 32 + nt * 8 + g;
                    uint32_t b0 = *(const uint32_t*)&vT[hrow * ASTH + col    ];
                    uint32_t b1 = *(const uint32_t*)&vT[hrow * ASTH + col + 8];
                    mma16(o[nt], pa, b0, b1);
                }
            }

            // store prefetched tiles into the other buffer (no race: its readers
            // finished before the end-of-previous-iteration barrier)
            if (sb < tb) {
                #pragma unroll
                for (int i = 0; i < 4; ++i)
                    *(uint2*)&qsn[qrow[i] * ASTH + qcol[i]] = qrh[i];
                #pragma unroll
                for (int r = 0; r < 4; ++r) {
                    int hh = lh + r * 16;
                    __half2 p0 = *(__half2*)&vrh[2 * r];
                    __half2 p1 = *(__half2*)&vrh[2 * r + 1];
                    vTn[(hh + 0) * ASTH + lr] = __low2half(p0);
                    vTn[(hh + 1) * ASTH + lr] = __high2half(p0);
                    vTn[(hh + 2) * ASTH + lr] = __low2half(p1);
                    vTn[(hh + 3) * ASTH + lr] = __high2half(p1);
                }
            }
            __syncthreads();   // O-MMA (Ps/vT readers) done; next buffers visible
        }

        // write O tile
        {
            const size_t row0 = (size_t)b * SEQ + tb * 64 + trow;
            #pragma unroll
            for (int nt = 0; nt < 4; ++nt) {
                const int col = wn * 32 + nt * 8 + 2 * t;
                *(float2*)&out[(row0    ) * HEAD + col] = make_float2(o[nt][0], o[nt][1]);
                *(float2*)&out[(row0 + 8) * HEAD + col] = make_float2(o[nt][2], o[nt][3]);
            }
        }
        __syncthreads();   // before next hf overwrites ks/buffers
    }
}

// ---------------------------------------------------------------------------
extern "C" void kernel_launch(void* const* d_in, const int* in_sizes, int n_in,
                              void* d_out, int out_size)
{
    const float* x  = (const float*)d_in[0];
    const float* Wk = (const float*)d_in[1];
    const float* bk = (const float*)d_in[2];
    const float* Wq = (const float*)d_in[3];
    const float* bq = (const float*)d_in[4];
    const float* Wv = (const float*)d_in[5];
    const float* bv = (const float*)d_in[6];
    float* out = (float*)d_out;

    static int init = 0;
    if (!init) {
        cudaFuncSetAttribute(attn_kernel, cudaFuncAttributeMaxDynamicSharedMemorySize, ATTN_SMEM);
        init = 1;
    }

    dim3 wg(NEMB / 16, 3);
    wt_kernel<<<wg, 256>>>(Wk, Wq, Wv);

    proj_mma_kernel<<<MTOT / 128, 256>>>(x, bk, bq, bv);

    dim3 ag(NTB / 2, BATCH);
    attn_kernel<<<ag, 256, ATTN_SMEM>>>(out);
}

// round 10
// speedup vs baseline: 1.6563x; 1.2661x over previous
#include <cuda_runtime.h>
#include <cuda_fp16.h>
#include <cstdint>
#include <math.h>

#define HEAD 64
#define NEMB 1024
#define BATCH 8
#define SEQ   2048
#define MTOT  (BATCH*SEQ)   // 16384
#define NTB   (SEQ/64)      // 32 t-blocks per batch

// scratch: projected k,q,v fp16 (6.3 MB) + transposed fp16 weights
__device__ __half g_kqv[3][MTOT][HEAD];
__device__ __half g_Wh[3][HEAD][NEMB];   // Wh[p][n][k] = half(W[p][k][n])

// D += A*B : m16n8k16 fp16 inputs, fp32 accum
__device__ __forceinline__ void mma16(float c[4], const uint32_t a[4], uint32_t b0, uint32_t b1) {
    asm volatile(
        "mma.sync.aligned.m16n8k16.row.col.f32.f16.f16.f32 "
        "{%0,%1,%2,%3}, {%4,%5,%6,%7}, {%8,%9}, {%0,%1,%2,%3};"
        : "+f"(c[0]), "+f"(c[1]), "+f"(c[2]), "+f"(c[3])
        : "r"(a[0]), "r"(a[1]), "r"(a[2]), "r"(a[3]), "r"(b0), "r"(b1));
}

__device__ __forceinline__ uint32_t f2h2(float a, float b) {
    __half2 h = __floats2half2_rn(a, b);
    return *(uint32_t*)&h;
}

// ---------------------------------------------------------------------------
// W transpose + fp16 round:  g_Wh[p][n][k] = half(W[p][k][n])
// grid (64, 3): each block transposes a 16(k) x 64(n) tile.
// ---------------------------------------------------------------------------
__global__ __launch_bounds__(256) void wt_kernel(
    const float* __restrict__ Wk, const float* __restrict__ Wq, const float* __restrict__ Wv)
{
    __shared__ float t[64][17];
    const float* __restrict__ W = (blockIdx.y == 0) ? Wk : ((blockIdx.y == 1) ? Wq : Wv);
    const int k0 = blockIdx.x * 16;
    const int tid = threadIdx.x;
    #pragma unroll
    for (int i = 0; i < 4; ++i) {
        int idx = i * 256 + tid;
        int kk = idx >> 6, n = idx & 63;
        t[n][kk] = W[(size_t)(k0 + kk) * HEAD + n];
    }
    __syncthreads();
    #pragma unroll
    for (int i = 0; i < 4; ++i) {
        int idx = i * 256 + tid;
        int n = idx >> 4, kk = idx & 15;
        g_Wh[blockIdx.y][n][k0 + kk] = __float2half_rn(t[n][kk]);
    }
}

// ---------------------------------------------------------------------------
// Projection via fp16 mma m16n8k16. CTA: 128(m) x 192(n=3x64), K chunk 32.
// 256 threads, 8 warps 4(m) x 2(n). Ping-pong smem buffers, 1 barrier/chunk.
// smem row stride 40 halves: word pattern 20g+t mod 32 all-distinct (no
// conflicts); 80-byte rows keep uint4 stores 16B-aligned.
// ---------------------------------------------------------------------------
#define PST 40
#define PROJ_X_H   (128 * PST)          // halves per x buffer
#define PROJ_W_H   (192 * PST)          // halves per w buffer
#define PROJ_SMEM  ((2 * PROJ_X_H + 2 * PROJ_W_H) * 2)   // 51200 B

__global__ __launch_bounds__(256, 1) void proj_mma_kernel(
    const float* __restrict__ x,
    const float* __restrict__ bk, const float* __restrict__ bq, const float* __restrict__ bv)
{
    extern __shared__ __half psm[];
    __half* xsb = psm;                   // 2 x [128][PST]
    __half* wsb = psm + 2 * PROJ_X_H;    // 2 x [192][PST]

    const int tid  = threadIdx.x;
    const int wid  = tid >> 5, lane = tid & 31;
    const int wm   = wid >> 1, wn = wid & 1;
    const int g    = lane >> 2, t = lane & 3;
    const int m0   = blockIdx.x * 128;

    // loader indices: x -> 4 float4 (convert to 4 halves each), w -> 3 uint4 (8 halves)
    int xrow[4], xcol[4], wrow[3], wcol[3];
    #pragma unroll
    for (int i = 0; i < 4; ++i) { int idx = i * 256 + tid; xrow[i] = idx >> 3; xcol[i] = (idx & 7) * 4; }
    #pragma unroll
    for (int i = 0; i < 3; ++i) { int idx = i * 256 + tid; wrow[i] = idx >> 2; wcol[i] = (idx & 3) * 8; }

    float c[2][12][4];
    #pragma unroll
    for (int mt = 0; mt < 2; ++mt)
        #pragma unroll
        for (int nt = 0; nt < 12; ++nt)
            #pragma unroll
            for (int r = 0; r < 4; ++r) c[mt][nt][r] = 0.f;

    uint2 xr[4];
    uint4 wr[3];

    // prologue: chunk 0 -> buffer 0
    #pragma unroll
    for (int i = 0; i < 4; ++i) {
        float4 v = *(const float4*)&x[(size_t)(m0 + xrow[i]) * NEMB + xcol[i]];
        xr[i].x = f2h2(v.x, v.y); xr[i].y = f2h2(v.z, v.w);
    }
    #pragma unroll
    for (int i = 0; i < 3; ++i)
        wr[i] = *(const uint4*)&g_Wh[wrow[i] >> 6][wrow[i] & 63][wcol[i]];
    #pragma unroll
    for (int i = 0; i < 4; ++i)
        *(uint2*)&xsb[xrow[i] * PST + xcol[i]] = xr[i];
    #pragma unroll
    for (int i = 0; i < 3; ++i)
        *(uint4*)&wsb[wrow[i] * PST + wcol[i]] = wr[i];
    __syncthreads();

    for (int ch = 0; ch < 32; ++ch) {
        const int cur = ch & 1;
        __half* xs = xsb + cur * PROJ_X_H;
        __half* ws = wsb + cur * PROJ_W_H;
        __half* xsn = xsb + (cur ^ 1) * PROJ_X_H;
        __half* wsn = wsb + (cur ^ 1) * PROJ_W_H;

        // prefetch next chunk into registers
        if (ch < 31) {
            const int k1 = (ch + 1) * 32;
            #pragma unroll
            for (int i = 0; i < 4; ++i) {
                float4 v = *(const float4*)&x[(size_t)(m0 + xrow[i]) * NEMB + k1 + xcol[i]];
                xr[i].x = f2h2(v.x, v.y); xr[i].y = f2h2(v.z, v.w);
            }
            #pragma unroll
            for (int i = 0; i < 3; ++i)
                wr[i] = *(const uint4*)&g_Wh[wrow[i] >> 6][wrow[i] & 63][k1 + wcol[i]];
        }

        // A fragments: 2 m-tiles x 2 k-tiles (k16)
        uint32_t A[2][2][4];
        #pragma unroll
        for (int mt = 0; mt < 2; ++mt) {
            const int row = wm * 32 + mt * 16 + g;
            #pragma unroll
            for (int kt = 0; kt < 2; ++kt) {
                const int col = kt * 16 + 2 * t;
                A[mt][kt][0] = *(const uint32_t*)&xs[(row    ) * PST + col    ];
                A[mt][kt][1] = *(const uint32_t*)&xs[(row + 8) * PST + col    ];
                A[mt][kt][2] = *(const uint32_t*)&xs[(row    ) * PST + col + 8];
                A[mt][kt][3] = *(const uint32_t*)&xs[(row + 8) * PST + col + 8];
            }
        }
        #pragma unroll
        for (int kt = 0; kt < 2; ++kt) {
            #pragma unroll
            for (int nt = 0; nt < 12; ++nt) {
                const int ng = wn * 96 + nt * 8 + g;
                const int col = kt * 16 + 2 * t;
                uint32_t b0 = *(const uint32_t*)&ws[ng * PST + col    ];
                uint32_t b1 = *(const uint32_t*)&ws[ng * PST + col + 8];
                mma16(c[0][nt], A[0][kt], b0, b1);
                mma16(c[1][nt], A[1][kt], b0, b1);
            }
        }

        // store prefetched chunk into the other buffer (its readers finished
        // before the previous barrier), then one barrier
        if (ch < 31) {
            #pragma unroll
            for (int i = 0; i < 4; ++i)
                *(uint2*)&xsn[xrow[i] * PST + xcol[i]] = xr[i];
            #pragma unroll
            for (int i = 0; i < 3; ++i)
                *(uint4*)&wsn[wrow[i] * PST + wcol[i]] = wr[i];
        }
        __syncthreads();
    }

    // epilogue: fp32 bias add, fp16 store
    const float* biases[3] = {bk, bq, bv};
    #pragma unroll
    for (int nt = 0; nt < 12; ++nt) {
        const int ng0 = wn * 96 + nt * 8;
        const int p = ng0 >> 6;
        const int n = (ng0 & 63) + 2 * t;
        const float* __restrict__ bias = biases[p];
        const float b0 = bias[n], b1 = bias[n + 1];
        #pragma unroll
        for (int mt = 0; mt < 2; ++mt) {
            const int row = m0 + wm * 32 + mt * 16 + g;
            *(uint32_t*)&g_kqv[p][row    ][n] = f2h2(c[mt][nt][0] + b0, c[mt][nt][1] + b1);
            *(uint32_t*)&g_kqv[p][row + 8][n] = f2h2(c[mt][nt][2] + b0, c[mt][nt][3] + b1);
        }
    }
}

// ---------------------------------------------------------------------------
// Attention via fp16 mma m16n8k16 (fp32 accum). 256 threads, 64x64 tiles,
// CTA handles t-blocks {i, 31-i} sequentially; grid (16,8), one wave.
// k/q/v already fp16 in g_kqv: loaders are pure copies (no conversion).
// Q/V double-buffered -> 2 barriers per s-iteration. Row stride 72 halves.
// ---------------------------------------------------------------------------
#define ASTH 72
#define TILE_H (64 * ASTH)                  // halves per tile
#define ATTN_SMEM (6 * TILE_H * 2)          // ks + 2*qs + 2*vT + Ps = 55296 B

__device__ __forceinline__ float softplus_f(float x) {
    return fmaxf(x, 0.f) + __logf(1.f + __expf(-fabsf(x)));
}

__global__ __launch_bounds__(256, 1) void attn_kernel(float* __restrict__ out)
{
    extern __shared__ __half smh[];
    __half* ks  = smh;                       // [64][ASTH]  K tile [t][h]
    __half* qsb = smh + TILE_H;              // 2 x [64][ASTH]  Q tiles [s][h]
    __half* vTb = smh + 3 * TILE_H;          // 2 x [64][ASTH]  V transposed [h][s]
    __half* Ps  = smh + 5 * TILE_H;          // [64][ASTH]  P tile [t][s]

    const int b    = blockIdx.y;
    const int tid  = threadIdx.x;
    const int wid  = tid >> 5, lane = tid & 31;
    const int wm   = wid >> 1, wn = wid & 1;
    const int g    = lane >> 2, t = lane & 3;
    const int lr   = tid & 63;               // V loader row (s)
    const int lh   = (tid >> 6) * 4;         // V loader col base (h)
    const int trow = wm * 16 + g;

    int qrow[4], qcol[4];
    #pragma unroll
    for (int i = 0; i < 4; ++i) { int idx = i * 256 + tid; qrow[i] = idx >> 4; qcol[i] = (idx & 15) * 4; }

    const __half* __restrict__ Kg = &g_kqv[0][(size_t)b * SEQ][0];
    const __half* __restrict__ Qg = &g_kqv[1][(size_t)b * SEQ][0];
    const __half* __restrict__ Vg = &g_kqv[2][(size_t)b * SEQ][0];

    for (int hf = 0; hf < 2; ++hf) {
        const int tb = hf ? (NTB - 1 - (int)blockIdx.x) : (int)blockIdx.x;

        // K tile [t][h]
        #pragma unroll
        for (int i = 0; i < 4; ++i) {
            uint2 u = *(const uint2*)&Kg[(size_t)(tb * 64 + qrow[i]) * HEAD + qcol[i]];
            *(uint2*)&ks[qrow[i] * ASTH + qcol[i]] = u;
        }

        // prologue: sb=0 Q/V into buffer 0
        {
            #pragma unroll
            for (int i = 0; i < 4; ++i) {
                uint2 u = *(const uint2*)&Qg[(size_t)qrow[i] * HEAD + qcol[i]];
                *(uint2*)&qsb[qrow[i] * ASTH + qcol[i]] = u;
            }
            #pragma unroll
            for (int r = 0; r < 4; ++r) {
                int hh = lh + r * 16;
                uint2 u = *(const uint2*)&Vg[(size_t)lr * HEAD + hh];
                __half2 p0 = *(__half2*)&u.x;
                __half2 p1 = *(__half2*)&u.y;
                vTb[(hh + 0) * ASTH + lr] = __low2half(p0);
                vTb[(hh + 1) * ASTH + lr] = __high2half(p0);
                vTb[(hh + 2) * ASTH + lr] = __low2half(p1);
                vTb[(hh + 3) * ASTH + lr] = __high2half(p1);
            }
        }
        __syncthreads();

        // K A-fragments, resident across the s-loop (4 kt of k16)
        uint32_t A[4][4];
        #pragma unroll
        for (int kt = 0; kt < 4; ++kt) {
            const int col = kt * 16 + 2 * t;
            A[kt][0] = *(const uint32_t*)&ks[(trow    ) * ASTH + col    ];
            A[kt][1] = *(const uint32_t*)&ks[(trow + 8) * ASTH + col    ];
            A[kt][2] = *(const uint32_t*)&ks[(trow    ) * ASTH + col + 8];
            A[kt][3] = *(const uint32_t*)&ks[(trow + 8) * ASTH + col + 8];
        }

        float o[4][4];
        #pragma unroll
        for (int nt = 0; nt < 4; ++nt)
            #pragma unroll
            for (int r = 0; r < 4; ++r) o[nt][r] = 0.f;

        uint2 qrh[4], vrh[4];

        for (int sb = 0; sb <= tb; ++sb) {
            const int cur = sb & 1;
            __half* qs  = qsb + cur * TILE_H;
            __half* vT  = vTb + cur * TILE_H;
            __half* qsn = qsb + (cur ^ 1) * TILE_H;
            __half* vTn = vTb + (cur ^ 1) * TILE_H;

            // prefetch next Q/V (pure fp16 copies)
            if (sb < tb) {
                const size_t s1 = (size_t)(sb + 1) * 64;
                #pragma unroll
                for (int i = 0; i < 4; ++i)
                    qrh[i] = *(const uint2*)&Qg[(s1 + qrow[i]) * HEAD + qcol[i]];
                #pragma unroll
                for (int r = 0; r < 4; ++r)
                    vrh[r] = *(const uint2*)&Vg[(s1 + lr) * HEAD + (lh + r * 16)];
            }

            // S = K . Q^T  (contract over h)
            float s_c[4][4];
            #pragma unroll
            for (int nt = 0; nt < 4; ++nt)
                #pragma unroll
                for (int r = 0; r < 4; ++r) s_c[nt][r] = 0.f;
            #pragma unroll
            for (int kt = 0; kt < 4; ++kt) {
                const int col = kt * 16 + 2 * t;
                #pragma unroll
                for (int nt = 0; nt < 4; ++nt) {
                    const int srow = wn * 32 + nt * 8 + g;
                    uint32_t b0 = *(const uint32_t*)&qs[srow * ASTH + col    ];
                    uint32_t b1 = *(const uint32_t*)&qs[srow * ASTH + col + 8];
                    mma16(s_c[nt], A[kt], b0, b1);
                }
            }

            // softplus + causal mask -> Ps [t][s] fp16
            const bool diag = (sb == tb);
            #pragma unroll
            for (int nt = 0; nt < 4; ++nt) {
                const int sc = wn * 32 + nt * 8 + 2 * t;
                float p0 = softplus_f(s_c[nt][0] * 0.03125f);
                float p1 = softplus_f(s_c[nt][1] * 0.03125f);
                float p2 = softplus_f(s_c[nt][2] * 0.03125f);
                float p3 = softplus_f(s_c[nt][3] * 0.03125f);
                if (diag) {
                    if (sc     > trow    ) p0 = 0.f;
                    if (sc + 1 > trow    ) p1 = 0.f;
                    if (sc     > trow + 8) p2 = 0.f;
                    if (sc + 1 > trow + 8) p3 = 0.f;
                }
                *(uint32_t*)&Ps[(trow    ) * ASTH + sc] = f2h2(p0, p1);
                *(uint32_t*)&Ps[(trow + 8) * ASTH + sc] = f2h2(p2, p3);
            }
            __syncthreads();   // Ps visible

            // O += P . V  (contract over s)
            #pragma unroll
            for (int kt = 0; kt < 4; ++kt) {
                const int col = kt * 16 + 2 * t;
                uint32_t pa[4];
                pa[0] = *(const uint32_t*)&Ps[(trow    ) * ASTH + col    ];
                pa[1] = *(const uint32_t*)&Ps[(trow + 8) * ASTH + col    ];
                pa[2] = *(const uint32_t*)&Ps[(trow    ) * ASTH + col + 8];
                pa[3] = *(const uint32_t*)&Ps[(trow + 8) * ASTH + col + 8];
                #pragma unroll
                for (int nt = 0; nt < 4; ++nt) {
                    const int hrow = wn * 32 + nt * 8 + g;
                    uint32_t b0 = *(const uint32_t*)&vT[hrow * ASTH + col    ];
                    uint32_t b1 = *(const uint32_t*)&vT[hrow * ASTH + col + 8];
                    mma16(o[nt], pa, b0, b1);
                }
            }

            // store prefetched tiles into the other buffer
            if (sb < tb) {
                #pragma unroll
                for (int i = 0; i < 4; ++i)
                    *(uint2*)&qsn[qrow[i] * ASTH + qcol[i]] = qrh[i];
                #pragma unroll
                for (int r = 0; r < 4; ++r) {
                    int hh = lh + r * 16;
                    __half2 p0 = *(__half2*)&vrh[r].x;
                    __half2 p1 = *(__half2*)&vrh[r].y;
                    vTn[(hh + 0) * ASTH + lr] = __low2half(p0);
                    vTn[(hh + 1) * ASTH + lr] = __high2half(p0);
                    vTn[(hh + 2) * ASTH + lr] = __low2half(p1);
                    vTn[(hh + 3) * ASTH + lr] = __high2half(p1);
                }
            }
            __syncthreads();   // O-MMA readers done; next buffers visible
        }

        // write O tile (fp32)
        {
            const size_t row0 = (size_t)b * SEQ + tb * 64 + trow;
            #pragma unroll
            for (int nt = 0; nt < 4; ++nt) {
                const int col = wn * 32 + nt * 8 + 2 * t;
                *(float2*)&out[(row0    ) * HEAD + col] = make_float2(o[nt][0], o[nt][1]);
                *(float2*)&out[(row0 + 8) * HEAD + col] = make_float2(o[nt][2], o[nt][3]);
            }
        }
        __syncthreads();   // before next hf overwrites ks/buffers
    }
}

// ---------------------------------------------------------------------------
extern "C" void kernel_launch(void* const* d_in, const int* in_sizes, int n_in,
                              void* d_out, int out_size)
{
    const float* x  = (const float*)d_in[0];
    const float* Wk = (const float*)d_in[1];
    const float* bk = (const float*)d_in[2];
    const float* Wq = (const float*)d_in[3];
    const float* bq = (const float*)d_in[4];
    const float* Wv = (const float*)d_in[5];
    const float* bv = (const float*)d_in[6];
    float* out = (float*)d_out;

    static int init = 0;
    if (!init) {
        cudaFuncSetAttribute(attn_kernel, cudaFuncAttributeMaxDynamicSharedMemorySize, ATTN_SMEM);
        cudaFuncSetAttribute(proj_mma_kernel, cudaFuncAttributeMaxDynamicSharedMemorySize, PROJ_SMEM);
        init = 1;
    }

    dim3 wg(NEMB / 16, 3);
    wt_kernel<<<wg, 256>>>(Wk, Wq, Wv);

    proj_mma_kernel<<<MTOT / 128, 256, PROJ_SMEM>>>(x, bk, bq, bv);

    dim3 ag(NTB / 2, BATCH);
    attn_kernel<<<ag, 256, ATTN_SMEM>>>(out);
}